// round 11
// baseline (speedup 1.0000x reference)
#include <cuda_runtime.h>
#include <cuda_fp16.h>
#include <math.h>
#include <stdint.h>

#define BB 2
#define LL 2048
#define DD 1024
#define HH 16
#define DHH 64
#define ROWS (BB*LL)   // 4096
#define LOG2E 1.44269504f

// Scratch (allocation-free rule: __device__ globals), fp16 intermediates
__device__ __half g_q[ROWS*DD];
__device__ __half g_k[ROWS*DD];
__device__ __half g_v[ROWS*DD];
__device__ __half g_attn[ROWS*DD];
__device__ __half g_xq[ROWS*DD];
__device__ __half g_xm[ROWS*DD];
__device__ __half g_wq[DD*DD];   // transposed [n][k]
__device__ __half g_wk[DD*DD];
__device__ __half g_wv[DD*DD];
__device__ __half g_wo[DD*DD];

// ===========================================================================
// Helpers
// ===========================================================================
__device__ __forceinline__ uint32_t smem_u32(const void* p) {
    uint32_t a;
    asm("{ .reg .u64 t; cvta.to.shared.u64 t, %1; cvt.u32.u64 %0, t; }"
        : "=r"(a) : "l"(p));
    return a;
}
__device__ __forceinline__ void mma_f16(float c[4],
    uint32_t a0, uint32_t a1, uint32_t a2, uint32_t a3,
    uint32_t b0, uint32_t b1)
{
    asm volatile(
        "mma.sync.aligned.m16n8k16.row.col.f32.f16.f16.f32 "
        "{%0,%1,%2,%3}, {%4,%5,%6,%7}, {%8,%9}, {%0,%1,%2,%3};"
        : "+f"(c[0]), "+f"(c[1]), "+f"(c[2]), "+f"(c[3])
        : "r"(a0), "r"(a1), "r"(a2), "r"(a3), "r"(b0), "r"(b1));
}
#define LDSM_X4(r, addr) \
    asm volatile("ldmatrix.sync.aligned.m8n8.x4.shared.b16 {%0,%1,%2,%3}, [%4];" \
        : "=r"((r)[0]), "=r"((r)[1]), "=r"((r)[2]), "=r"((r)[3]) : "r"(addr))
#define LDSM_X4_T(r, addr) \
    asm volatile("ldmatrix.sync.aligned.m8n8.x4.trans.shared.b16 {%0,%1,%2,%3}, [%4];" \
        : "=r"((r)[0]), "=r"((r)[1]), "=r"((r)[2]), "=r"((r)[3]) : "r"(addr))
__device__ __forceinline__ void cp_async16(uint32_t s, const void* g) {
    asm volatile("cp.async.cg.shared.global [%0], [%1], 16;" :: "r"(s), "l"(g));
}
#define CP_COMMIT() asm volatile("cp.async.commit_group;" ::: "memory")
#define CP_WAIT0()  asm volatile("cp.async.wait_group 0;" ::: "memory")
#define CP_WAIT1()  asm volatile("cp.async.wait_group 1;" ::: "memory")
__device__ __forceinline__ uint32_t pack_h2(float x, float y) {
    __half2 h = __floats2half2_rn(x, y);
    return *reinterpret_cast<uint32_t*>(&h);
}
__device__ __forceinline__ float ex2(float x) {   // raw MUFU.EX2 (exp2 domain)
    float r;
    asm("ex2.approx.ftz.f32 %0, %1;" : "=f"(r) : "f"(x));
    return r;
}

// ===========================================================================
// Prep kernels (fused via blockIdx.z)
// ===========================================================================
__global__ __launch_bounds__(256) void convert_h2(
    const float* __restrict__ s0, __half* __restrict__ d0,
    const float* __restrict__ s1, __half* __restrict__ d1, int n4)
{
    const float* src = blockIdx.z ? s1 : s0;
    __half* dst      = blockIdx.z ? d1 : d0;
    int i = blockIdx.x * blockDim.x + threadIdx.x;
    if (i < n4) {
        float4 v = reinterpret_cast<const float4*>(src)[i];
        reinterpret_cast<__half2*>(dst)[2 * i]     = __floats2half2_rn(v.x, v.y);
        reinterpret_cast<__half2*>(dst)[2 * i + 1] = __floats2half2_rn(v.z, v.w);
    }
}

__global__ __launch_bounds__(256) void transpose_h4(
    const float* __restrict__ W0, __half* __restrict__ T0,
    const float* __restrict__ W1, __half* __restrict__ T1,
    const float* __restrict__ W2, __half* __restrict__ T2,
    const float* __restrict__ W3, __half* __restrict__ T3)
{
    const float* W; __half* Wt;
    switch (blockIdx.z) {
        case 0:  W = W0; Wt = T0; break;
        case 1:  W = W1; Wt = T1; break;
        case 2:  W = W2; Wt = T2; break;
        default: W = W3; Wt = T3; break;
    }
    __shared__ float t[32][33];
    int x = blockIdx.x * 32 + threadIdx.x;
    int y = blockIdx.y * 32 + threadIdx.y;
    #pragma unroll
    for (int i = 0; i < 32; i += 8)
        t[threadIdx.y + i][threadIdx.x] = W[(long long)(y + i) * DD + x];
    __syncthreads();
    x = blockIdx.y * 32 + threadIdx.x;
    y = blockIdx.x * 32 + threadIdx.y;
    #pragma unroll
    for (int i = 0; i < 32; i += 8)
        Wt[(long long)(y + i) * DD + x] = __float2half_rn(t[threadIdx.x][threadIdx.y + i]);
}

// ===========================================================================
// fp16 mma GEMM core: 128x128x32 block, 128 thr (4 warps, 64x64 warp tile),
// 3-stage cp.async ring, one barrier per K-iter.
// ===========================================================================
#define GBK 32
#define PA 40
#define TILEH (128 * PA)

__device__ __forceinline__ void gemm_core(
    const __half* __restrict__ A, const __half* __restrict__ Bt,
    void* __restrict__ Cv, float scale, int out_half, __half* sm,
    long long bm, long long bn)
{
    const int tid = threadIdx.x, lane = tid & 31, wid = tid >> 5;
    const int wr = (wid & 1) * 64, wc = (wid >> 1) * 64;
    const int tg = lane >> 2, tk = lane & 3;

    const int aOff = (wr + (lane & 15)) * PA + ((lane & 16) ? 8 : 0);
    const int bOff = (wc + (lane & 7) + ((lane & 16) ? 8 : 0)) * PA
                     + ((lane & 8) ? 8 : 0);

    float c[4][8][4];
    #pragma unroll
    for (int mi = 0; mi < 4; mi++)
        #pragma unroll
        for (int nj = 0; nj < 8; nj++)
            #pragma unroll
            for (int r = 0; r < 4; r++) c[mi][nj][r] = 0.f;

    auto stage = [&](int s, int k0) {
        __half* a = sm + s * 2 * TILEH;
        __half* b = a + TILEH;
        #pragma unroll
        for (int it = 0; it < 4; it++) {
            int f = it * 128 + tid, row = f >> 2, ch = f & 3;
            cp_async16(smem_u32(a + row * PA + ch * 8),
                       A + (bm + row) * DD + k0 + ch * 8);
            cp_async16(smem_u32(b + row * PA + ch * 8),
                       Bt + (bn + row) * DD + k0 + ch * 8);
        }
    };

    stage(0, 0);       CP_COMMIT();
    stage(1, GBK);     CP_COMMIT();

    const int NKT = DD / GBK;  // 32
    for (int kt = 0; kt < NKT; kt++) {
        if (kt + 1 < NKT) { CP_WAIT1(); } else { CP_WAIT0(); }
        __syncthreads();
        if (kt + 2 < NKT) { stage((kt + 2) % 3, (kt + 2) * GBK); CP_COMMIT(); }

        int buf = kt % 3;
        const __half* a = sm + buf * 2 * TILEH;
        uint32_t aBase = smem_u32(a + aOff);
        uint32_t bBase = smem_u32(a + TILEH + bOff);

        #pragma unroll
        for (int k16 = 0; k16 < 2; k16++) {
            uint32_t av[4][4], bv[4][4];
            #pragma unroll
            for (int mi = 0; mi < 4; mi++)
                LDSM_X4(av[mi], aBase + (mi * 16 * PA + k16 * 16) * 2);
            #pragma unroll
            for (int p = 0; p < 4; p++)
                LDSM_X4(bv[p], bBase + (p * 16 * PA + k16 * 16) * 2);
            #pragma unroll
            for (int mi = 0; mi < 4; mi++)
                #pragma unroll
                for (int p = 0; p < 4; p++) {
                    mma_f16(c[mi][2 * p],     av[mi][0], av[mi][1], av[mi][2], av[mi][3],
                            bv[p][0], bv[p][1]);
                    mma_f16(c[mi][2 * p + 1], av[mi][0], av[mi][1], av[mi][2], av[mi][3],
                            bv[p][2], bv[p][3]);
                }
        }
    }

    #pragma unroll
    for (int mi = 0; mi < 4; mi++) {
        long long row = bm + wr + mi * 16 + tg;
        #pragma unroll
        for (int nj = 0; nj < 8; nj++) {
            long long col = bn + wc + nj * 8 + 2 * tk;
            if (out_half) {
                __half* C = (__half*)Cv;
                *reinterpret_cast<__half2*>(&C[row * DD + col]) =
                    __floats2half2_rn(c[mi][nj][0] * scale, c[mi][nj][1] * scale);
                *reinterpret_cast<__half2*>(&C[(row + 8) * DD + col]) =
                    __floats2half2_rn(c[mi][nj][2] * scale, c[mi][nj][3] * scale);
            } else {
                float* C = (float*)Cv;
                *reinterpret_cast<float2*>(&C[row * DD + col]) =
                    make_float2(c[mi][nj][0] * scale, c[mi][nj][1] * scale);
                *reinterpret_cast<float2*>(&C[(row + 8) * DD + col]) =
                    make_float2(c[mi][nj][2] * scale, c[mi][nj][3] * scale);
            }
        }
    }
}

__global__ __launch_bounds__(128, 2) void gemm_qkv(
    const __half* __restrict__ xq, const __half* __restrict__ xm,
    const __half* __restrict__ wq, const __half* __restrict__ wk,
    const __half* __restrict__ wv,
    __half* __restrict__ q, __half* __restrict__ k, __half* __restrict__ v)
{
    extern __shared__ __half sm[];
    const __half *A, *Bt; __half* C; float scale;
    switch (blockIdx.z) {
        // Q carries d_head^-0.5 AND the log2e fold for the exp2-domain softmax
        case 0:  A = xq; Bt = wq; C = q; scale = 0.125f * LOG2E; break;
        case 1:  A = xm; Bt = wk; C = k; scale = 1.0f;           break;
        default: A = xm; Bt = wv; C = v; scale = 1.0f;           break;
    }
    gemm_core(A, Bt, C, scale, 1, sm,
              (long long)blockIdx.y * 128, (long long)blockIdx.x * 128);
}

__global__ __launch_bounds__(128, 2) void gemm_out(
    const __half* __restrict__ A, const __half* __restrict__ Bt,
    float* __restrict__ C)
{
    extern __shared__ __half sm[];
    gemm_core(A, Bt, C, 1.0f, 0, sm,
              (long long)blockIdx.y * 128, (long long)blockIdx.x * 128);
}

// ===========================================================================
// Flash attention, fp16 mma, exp2-domain softmax. CTA = 128 q-rows, 4 warps,
// warp tile 32x64. 3 CTAs/SM (reg cap 170): Q frags reloaded from smem per
// tile instead of hoisted. fp32 bias (x log2e at prefetch, hidden under PV).
// ===========================================================================
#define PK 72

__global__ __launch_bounds__(128, 3) void attn_h(
    const __half* __restrict__ Q, const __half* __restrict__ K,
    const __half* __restrict__ V, const float* __restrict__ bias,
    __half* __restrict__ O)
{
    extern __shared__ __half sm[];
    __half* Qs = sm;                          // [128][72]
    __half* Ks = Qs + 128 * PK;               // [3][64][72]
    __half* Vs = Ks + 3 * 64 * PK;            // [3][64][72]

    const int tid = threadIdx.x, lane = tid & 31, wid = tid >> 5;
    const int tg = lane >> 2, tk = lane & 3;
    const int bh = blockIdx.y, b = bh >> 4, h = bh & 15;
    const int q0 = blockIdx.x * 128;
    const int wq0 = wid * 32;

    const __half* qbase = Q + ((long long)(b * LL + q0)) * DD + h * DHH;
    const __half* kbase = K + ((long long)(b * LL)) * DD + h * DHH;
    const __half* vbase = V + ((long long)(b * LL)) * DD + h * DHH;
    const float*  brow  = bias + (long long)(q0 + wq0 + tg) * LL + 2 * tk;

    const int aOffQ = (wq0 + (lane & 15)) * PK + ((lane & 16) ? 8 : 0);
    const int bOffK = ((lane & 7) + ((lane & 16) ? 8 : 0)) * PK + ((lane & 8) ? 8 : 0);
    const int bOffV = ((lane & 7) + ((lane & 8) ? 8 : 0)) * PK + ((lane & 16) ? 8 : 0);

    auto stageKV = [&](int buf, int kt) {
        __half* ks = Ks + buf * 64 * PK;
        __half* vs = Vs + buf * 64 * PK;
        const int k0 = kt * 64;
        #pragma unroll
        for (int it = 0; it < 4; it++) {
            int f = it * 128 + tid, row = f >> 3, ch = f & 7;
            cp_async16(smem_u32(ks + row * PK + ch * 8),
                       kbase + (long long)(k0 + row) * DD + ch * 8);
            cp_async16(smem_u32(vs + row * PK + ch * 8),
                       vbase + (long long)(k0 + row) * DD + ch * 8);
        }
    };

    #pragma unroll
    for (int it = 0; it < 8; it++) {
        int f = it * 128 + tid, row = f >> 3, ch = f & 7;
        cp_async16(smem_u32(Qs + row * PK + ch * 8),
                   qbase + (long long)row * DD + ch * 8);
    }
    stageKV(0, 0);
    CP_COMMIT();
    stageKV(1, 1);
    CP_COMMIT();

    float m[2][2], l[2][2];
    float o[2][8][4];
    #pragma unroll
    for (int mi = 0; mi < 2; mi++) {
        m[mi][0] = -INFINITY; m[mi][1] = -INFINITY;
        l[mi][0] = 0.f;       l[mi][1] = 0.f;
        #pragma unroll
        for (int j = 0; j < 8; j++)
            #pragma unroll
            for (int r = 0; r < 4; r++) o[mi][j][r] = 0.f;
    }

    float s[2][8][4];
    auto load_bias = [&](int kt) {   // bias * log2e (exp2-domain)
        #pragma unroll
        for (int mi = 0; mi < 2; mi++) {
            const float* bp = brow + (long long)(mi * 16) * LL + kt * 64;
            #pragma unroll
            for (int nj = 0; nj < 8; nj++) {
                float2 b0 = *reinterpret_cast<const float2*>(bp + nj * 8);
                float2 b1 = *reinterpret_cast<const float2*>(bp + 8 * (long long)LL + nj * 8);
                s[mi][nj][0] = b0.x * LOG2E; s[mi][nj][1] = b0.y * LOG2E;
                s[mi][nj][2] = b1.x * LOG2E; s[mi][nj][3] = b1.y * LOG2E;
            }
        }
    };
    load_bias(0);

    CP_WAIT1();
    __syncthreads();
    const uint32_t qBase = smem_u32(Qs + aOffQ);

    const int NT = LL / 64;  // 32
    for (int kt = 0; kt < NT; kt++) {
        if (kt > 0) {
            if (kt + 1 < NT) { CP_WAIT1(); } else { CP_WAIT0(); }
            __syncthreads();
        }
        if (kt + 2 < NT) { stageKV((kt + 2) % 3, kt + 2); CP_COMMIT(); }

        int buf = kt % 3;
        const uint32_t kBase = smem_u32(Ks + buf * 64 * PK + bOffK);
        const uint32_t vBase = smem_u32(Vs + buf * 64 * PK + bOffV);

        // S = bias*log2e + Q' @ K^T  (Q' pre-scaled by 0.125*log2e)
        #pragma unroll
        for (int k16 = 0; k16 < 4; k16++) {
            uint32_t qa[4], qb[4];
            LDSM_X4(qa, qBase + (k16 * 16) * 2);
            LDSM_X4(qb, qBase + (16 * PK + k16 * 16) * 2);
            #pragma unroll
            for (int p = 0; p < 4; p++) {
                uint32_t bv[4];
                LDSM_X4(bv, kBase + (p * 16 * PK + k16 * 16) * 2);
                mma_f16(s[0][2 * p],     qa[0], qa[1], qa[2], qa[3], bv[0], bv[1]);
                mma_f16(s[0][2 * p + 1], qa[0], qa[1], qa[2], qa[3], bv[2], bv[3]);
                mma_f16(s[1][2 * p],     qb[0], qb[1], qb[2], qb[3], bv[0], bv[1]);
                mma_f16(s[1][2 * p + 1], qb[0], qb[1], qb[2], qb[3], bv[2], bv[3]);
            }
        }

        // Online softmax (exp2 domain) per m-fragment
        uint32_t pv[2][4][4];
        #pragma unroll
        for (int mi = 0; mi < 2; mi++) {
            float r0 = -INFINITY, r1 = -INFINITY;
            #pragma unroll
            for (int nj = 0; nj < 8; nj++) {
                r0 = fmaxf(r0, fmaxf(s[mi][nj][0], s[mi][nj][1]));
                r1 = fmaxf(r1, fmaxf(s[mi][nj][2], s[mi][nj][3]));
            }
            r0 = fmaxf(r0, __shfl_xor_sync(0xffffffffu, r0, 1));
            r0 = fmaxf(r0, __shfl_xor_sync(0xffffffffu, r0, 2));
            r1 = fmaxf(r1, __shfl_xor_sync(0xffffffffu, r1, 1));
            r1 = fmaxf(r1, __shfl_xor_sync(0xffffffffu, r1, 2));
            float m0n = fmaxf(m[mi][0], r0), m1n = fmaxf(m[mi][1], r1);
            float al0 = ex2(m[mi][0] - m0n), al1 = ex2(m[mi][1] - m1n);
            float s0 = 0.f, s1 = 0.f;
            #pragma unroll
            for (int nj = 0; nj < 8; nj++) {
                s[mi][nj][0] = ex2(s[mi][nj][0] - m0n);
                s[mi][nj][1] = ex2(s[mi][nj][1] - m0n);
                s[mi][nj][2] = ex2(s[mi][nj][2] - m1n);
                s[mi][nj][3] = ex2(s[mi][nj][3] - m1n);
                s0 += s[mi][nj][0] + s[mi][nj][1];
                s1 += s[mi][nj][2] + s[mi][nj][3];
            }
            s0 += __shfl_xor_sync(0xffffffffu, s0, 1);
            s0 += __shfl_xor_sync(0xffffffffu, s0, 2);
            s1 += __shfl_xor_sync(0xffffffffu, s1, 1);
            s1 += __shfl_xor_sync(0xffffffffu, s1, 2);
            l[mi][0] = l[mi][0] * al0 + s0;
            l[mi][1] = l[mi][1] * al1 + s1;
            m[mi][0] = m0n;  m[mi][1] = m1n;
            #pragma unroll
            for (int nj = 0; nj < 8; nj++) {
                o[mi][nj][0] *= al0; o[mi][nj][1] *= al0;
                o[mi][nj][2] *= al1; o[mi][nj][3] *= al1;
            }
            #pragma unroll
            for (int j = 0; j < 4; j++) {
                pv[mi][j][0] = pack_h2(s[mi][2 * j][0],     s[mi][2 * j][1]);
                pv[mi][j][1] = pack_h2(s[mi][2 * j][2],     s[mi][2 * j][3]);
                pv[mi][j][2] = pack_h2(s[mi][2 * j + 1][0], s[mi][2 * j + 1][1]);
                pv[mi][j][3] = pack_h2(s[mi][2 * j + 1][2], s[mi][2 * j + 1][3]);
            }
        }

        load_bias((kt + 1) & (NT - 1));

        // O += P @ V
        #pragma unroll
        for (int k16 = 0; k16 < 4; k16++) {
            #pragma unroll
            for (int p = 0; p < 4; p++) {
                uint32_t bv[4];
                LDSM_X4_T(bv, vBase + (k16 * 16 * PK + p * 16) * 2);
                #pragma unroll
                for (int mi = 0; mi < 2; mi++) {
                    mma_f16(o[mi][2 * p],     pv[mi][k16][0], pv[mi][k16][1],
                            pv[mi][k16][2], pv[mi][k16][3], bv[0], bv[1]);
                    mma_f16(o[mi][2 * p + 1], pv[mi][k16][0], pv[mi][k16][1],
                            pv[mi][k16][2], pv[mi][k16][3], bv[2], bv[3]);
                }
            }
        }
    }

    #pragma unroll
    for (int mi = 0; mi < 2; mi++) {
        float inv0 = 1.f / l[mi][0], inv1 = 1.f / l[mi][1];
        __half* ob = O + ((long long)(b * LL + q0 + wq0 + mi * 16 + tg)) * DD + h * DHH;
        #pragma unroll
        for (int nj = 0; nj < 8; nj++) {
            *reinterpret_cast<__half2*>(&ob[nj * 8 + 2 * tk]) =
                __floats2half2_rn(o[mi][nj][0] * inv0, o[mi][nj][1] * inv0);
            *reinterpret_cast<__half2*>(&ob[8 * DD + nj * 8 + 2 * tk]) =
                __floats2half2_rn(o[mi][nj][2] * inv1, o[mi][nj][3] * inv1);
        }
    }
}

// ---------------------------------------------------------------------------
extern "C" void kernel_launch(void* const* d_in, const int* in_sizes, int n_in,
                              void* d_out, int out_size)
{
    const float* xq   = (const float*)d_in[0];
    const float* xm   = (const float*)d_in[1];
    const float* bias = (const float*)d_in[2];
    const float* Wq   = (const float*)d_in[3];
    const float* Wk   = (const float*)d_in[4];
    const float* Wv   = (const float*)d_in[5];
    const float* Wo   = (const float*)d_in[6];
    float* out = (float*)d_out;

    __half *q, *k, *v, *attn, *hxq, *hxm, *twq, *twk, *twv, *two;
    cudaGetSymbolAddress((void**)&q,    g_q);
    cudaGetSymbolAddress((void**)&k,    g_k);
    cudaGetSymbolAddress((void**)&v,    g_v);
    cudaGetSymbolAddress((void**)&attn, g_attn);
    cudaGetSymbolAddress((void**)&hxq,  g_xq);
    cudaGetSymbolAddress((void**)&hxm,  g_xm);
    cudaGetSymbolAddress((void**)&twq,  g_wq);
    cudaGetSymbolAddress((void**)&twk,  g_wk);
    cudaGetSymbolAddress((void**)&twv,  g_wv);
    cudaGetSymbolAddress((void**)&two,  g_wo);

    // 1) Prep (2 launches)
    const int N4 = ROWS * DD / 4;
    dim3 cg((N4 + 255) / 256, 1, 2);
    convert_h2<<<cg, 256>>>(xq, hxq, xm, hxm, N4);
    dim3 tb(32, 8), tg(DD / 32, DD / 32, 4);
    transpose_h4<<<tg, tb>>>(Wq, twq, Wk, twk, Wv, twv, Wo, two);

    // 2) Fused Q/K/V projections
    const int GEMM_SMEM = 3 * 2 * TILEH * 2;  // 61440
    cudaFuncSetAttribute(gemm_qkv, cudaFuncAttributeMaxDynamicSharedMemorySize, GEMM_SMEM);
    cudaFuncSetAttribute(gemm_out, cudaFuncAttributeMaxDynamicSharedMemorySize, GEMM_SMEM);
    dim3 gq(DD / 128, ROWS / 128, 3);
    gemm_qkv<<<gq, 128, GEMM_SMEM>>>(hxq, hxm, twq, twk, twv, q, k, v);

    // 3) Attention (fp32 bias, exp2 domain, 3 CTAs/SM)
    const int ATTN_SMEM = (128 * PK + 3 * 64 * PK + 3 * 64 * PK) * 2;  // 73728
    cudaFuncSetAttribute(attn_h, cudaFuncAttributeMaxDynamicSharedMemorySize, ATTN_SMEM);
    dim3 ga(LL / 128, BB * HH);
    attn_h<<<ga, 128, ATTN_SMEM>>>(q, k, v, bias, attn);

    // 4) Output projection (fp32 out — final answer)
    dim3 gg(DD / 128, ROWS / 128);
    gemm_out<<<gg, 128, GEMM_SMEM>>>(attn, two, out);
}

// round 12
// speedup vs baseline: 1.1272x; 1.1272x over previous
#include <cuda_runtime.h>
#include <cuda_fp16.h>
#include <math.h>
#include <stdint.h>

#define BB 2
#define LL 2048
#define DD 1024
#define HH 16
#define DHH 64
#define ROWS (BB*LL)   // 4096
#define LOG2E 1.44269504f

// Scratch (allocation-free rule: __device__ globals), fp16 intermediates
__device__ __half g_q[ROWS*DD];
__device__ __half g_k[ROWS*DD];
__device__ __half g_v[ROWS*DD];
__device__ __half g_attn[ROWS*DD];
__device__ __half g_xq[ROWS*DD];
__device__ __half g_xm[ROWS*DD];
__device__ __half g_wq[DD*DD];   // transposed [n][k]
__device__ __half g_wk[DD*DD];
__device__ __half g_wv[DD*DD];
__device__ __half g_wo[DD*DD];

// ===========================================================================
// Helpers
// ===========================================================================
__device__ __forceinline__ uint32_t smem_u32(const void* p) {
    uint32_t a;
    asm("{ .reg .u64 t; cvta.to.shared.u64 t, %1; cvt.u32.u64 %0, t; }"
        : "=r"(a) : "l"(p));
    return a;
}
__device__ __forceinline__ void mma_f16(float c[4],
    uint32_t a0, uint32_t a1, uint32_t a2, uint32_t a3,
    uint32_t b0, uint32_t b1)
{
    asm volatile(
        "mma.sync.aligned.m16n8k16.row.col.f32.f16.f16.f32 "
        "{%0,%1,%2,%3}, {%4,%5,%6,%7}, {%8,%9}, {%0,%1,%2,%3};"
        : "+f"(c[0]), "+f"(c[1]), "+f"(c[2]), "+f"(c[3])
        : "r"(a0), "r"(a1), "r"(a2), "r"(a3), "r"(b0), "r"(b1));
}
#define LDSM_X4(r, addr) \
    asm volatile("ldmatrix.sync.aligned.m8n8.x4.shared.b16 {%0,%1,%2,%3}, [%4];" \
        : "=r"((r)[0]), "=r"((r)[1]), "=r"((r)[2]), "=r"((r)[3]) : "r"(addr))
#define LDSM_X4_T(r, addr) \
    asm volatile("ldmatrix.sync.aligned.m8n8.x4.trans.shared.b16 {%0,%1,%2,%3}, [%4];" \
        : "=r"((r)[0]), "=r"((r)[1]), "=r"((r)[2]), "=r"((r)[3]) : "r"(addr))
__device__ __forceinline__ void cp_async16(uint32_t s, const void* g) {
    asm volatile("cp.async.cg.shared.global [%0], [%1], 16;" :: "r"(s), "l"(g));
}
#define CP_COMMIT() asm volatile("cp.async.commit_group;" ::: "memory")
#define CP_WAIT0()  asm volatile("cp.async.wait_group 0;" ::: "memory")
#define CP_WAIT1()  asm volatile("cp.async.wait_group 1;" ::: "memory")
__device__ __forceinline__ uint32_t pack_h2(float x, float y) {
    __half2 h = __floats2half2_rn(x, y);
    return *reinterpret_cast<uint32_t*>(&h);
}
__device__ __forceinline__ float ex2(float x) {   // raw MUFU.EX2 (exp2 domain)
    float r;
    asm("ex2.approx.ftz.f32 %0, %1;" : "=f"(r) : "f"(x));
    return r;
}

// ===========================================================================
// Prep kernels (fused via blockIdx.z)
// ===========================================================================
__global__ __launch_bounds__(256) void convert_h2(
    const float* __restrict__ s0, __half* __restrict__ d0,
    const float* __restrict__ s1, __half* __restrict__ d1, int n4)
{
    const float* src = blockIdx.z ? s1 : s0;
    __half* dst      = blockIdx.z ? d1 : d0;
    int i = blockIdx.x * blockDim.x + threadIdx.x;
    if (i < n4) {
        float4 v = reinterpret_cast<const float4*>(src)[i];
        reinterpret_cast<__half2*>(dst)[2 * i]     = __floats2half2_rn(v.x, v.y);
        reinterpret_cast<__half2*>(dst)[2 * i + 1] = __floats2half2_rn(v.z, v.w);
    }
}

__global__ __launch_bounds__(256) void transpose_h4(
    const float* __restrict__ W0, __half* __restrict__ T0,
    const float* __restrict__ W1, __half* __restrict__ T1,
    const float* __restrict__ W2, __half* __restrict__ T2,
    const float* __restrict__ W3, __half* __restrict__ T3)
{
    const float* W; __half* Wt;
    switch (blockIdx.z) {
        case 0:  W = W0; Wt = T0; break;
        case 1:  W = W1; Wt = T1; break;
        case 2:  W = W2; Wt = T2; break;
        default: W = W3; Wt = T3; break;
    }
    __shared__ float t[32][33];
    int x = blockIdx.x * 32 + threadIdx.x;
    int y = blockIdx.y * 32 + threadIdx.y;
    #pragma unroll
    for (int i = 0; i < 32; i += 8)
        t[threadIdx.y + i][threadIdx.x] = W[(long long)(y + i) * DD + x];
    __syncthreads();
    x = blockIdx.y * 32 + threadIdx.x;
    y = blockIdx.x * 32 + threadIdx.y;
    #pragma unroll
    for (int i = 0; i < 32; i += 8)
        Wt[(long long)(y + i) * DD + x] = __float2half_rn(t[threadIdx.x][threadIdx.y + i]);
}

// ===========================================================================
// fp16 mma GEMM core: 128x128x32 block, 128 thr (4 warps, 64x64 warp tile),
// 3-stage cp.async ring, one barrier per K-iter.
// ===========================================================================
#define GBK 32
#define PA 40
#define TILEH (128 * PA)

__device__ __forceinline__ void gemm_core(
    const __half* __restrict__ A, const __half* __restrict__ Bt,
    void* __restrict__ Cv, float scale, int out_half, __half* sm,
    long long bm, long long bn)
{
    const int tid = threadIdx.x, lane = tid & 31, wid = tid >> 5;
    const int wr = (wid & 1) * 64, wc = (wid >> 1) * 64;
    const int tg = lane >> 2, tk = lane & 3;

    const int aOff = (wr + (lane & 15)) * PA + ((lane & 16) ? 8 : 0);
    const int bOff = (wc + (lane & 7) + ((lane & 16) ? 8 : 0)) * PA
                     + ((lane & 8) ? 8 : 0);

    float c[4][8][4];
    #pragma unroll
    for (int mi = 0; mi < 4; mi++)
        #pragma unroll
        for (int nj = 0; nj < 8; nj++)
            #pragma unroll
            for (int r = 0; r < 4; r++) c[mi][nj][r] = 0.f;

    auto stage = [&](int s, int k0) {
        __half* a = sm + s * 2 * TILEH;
        __half* b = a + TILEH;
        #pragma unroll
        for (int it = 0; it < 4; it++) {
            int f = it * 128 + tid, row = f >> 2, ch = f & 3;
            cp_async16(smem_u32(a + row * PA + ch * 8),
                       A + (bm + row) * DD + k0 + ch * 8);
            cp_async16(smem_u32(b + row * PA + ch * 8),
                       Bt + (bn + row) * DD + k0 + ch * 8);
        }
    };

    stage(0, 0);       CP_COMMIT();
    stage(1, GBK);     CP_COMMIT();

    const int NKT = DD / GBK;  // 32
    for (int kt = 0; kt < NKT; kt++) {
        if (kt + 1 < NKT) { CP_WAIT1(); } else { CP_WAIT0(); }
        __syncthreads();
        if (kt + 2 < NKT) { stage((kt + 2) % 3, (kt + 2) * GBK); CP_COMMIT(); }

        int buf = kt % 3;
        const __half* a = sm + buf * 2 * TILEH;
        uint32_t aBase = smem_u32(a + aOff);
        uint32_t bBase = smem_u32(a + TILEH + bOff);

        #pragma unroll
        for (int k16 = 0; k16 < 2; k16++) {
            uint32_t av[4][4], bv[4][4];
            #pragma unroll
            for (int mi = 0; mi < 4; mi++)
                LDSM_X4(av[mi], aBase + (mi * 16 * PA + k16 * 16) * 2);
            #pragma unroll
            for (int p = 0; p < 4; p++)
                LDSM_X4(bv[p], bBase + (p * 16 * PA + k16 * 16) * 2);
            #pragma unroll
            for (int mi = 0; mi < 4; mi++)
                #pragma unroll
                for (int p = 0; p < 4; p++) {
                    mma_f16(c[mi][2 * p],     av[mi][0], av[mi][1], av[mi][2], av[mi][3],
                            bv[p][0], bv[p][1]);
                    mma_f16(c[mi][2 * p + 1], av[mi][0], av[mi][1], av[mi][2], av[mi][3],
                            bv[p][2], bv[p][3]);
                }
        }
    }

    #pragma unroll
    for (int mi = 0; mi < 4; mi++) {
        long long row = bm + wr + mi * 16 + tg;
        #pragma unroll
        for (int nj = 0; nj < 8; nj++) {
            long long col = bn + wc + nj * 8 + 2 * tk;
            if (out_half) {
                __half* C = (__half*)Cv;
                *reinterpret_cast<__half2*>(&C[row * DD + col]) =
                    __floats2half2_rn(c[mi][nj][0] * scale, c[mi][nj][1] * scale);
                *reinterpret_cast<__half2*>(&C[(row + 8) * DD + col]) =
                    __floats2half2_rn(c[mi][nj][2] * scale, c[mi][nj][3] * scale);
            } else {
                float* C = (float*)Cv;
                *reinterpret_cast<float2*>(&C[row * DD + col]) =
                    make_float2(c[mi][nj][0] * scale, c[mi][nj][1] * scale);
                *reinterpret_cast<float2*>(&C[(row + 8) * DD + col]) =
                    make_float2(c[mi][nj][2] * scale, c[mi][nj][3] * scale);
            }
        }
    }
}

__global__ __launch_bounds__(128, 2) void gemm_qkv(
    const __half* __restrict__ xq, const __half* __restrict__ xm,
    const __half* __restrict__ wq, const __half* __restrict__ wk,
    const __half* __restrict__ wv,
    __half* __restrict__ q, __half* __restrict__ k, __half* __restrict__ v)
{
    extern __shared__ __half sm[];
    const __half *A, *Bt; __half* C; float scale;
    switch (blockIdx.z) {
        // Q carries d_head^-0.5 AND the log2e fold for the exp2-domain softmax
        case 0:  A = xq; Bt = wq; C = q; scale = 0.125f * LOG2E; break;
        case 1:  A = xm; Bt = wk; C = k; scale = 1.0f;           break;
        default: A = xm; Bt = wv; C = v; scale = 1.0f;           break;
    }
    gemm_core(A, Bt, C, scale, 1, sm,
              (long long)blockIdx.y * 128, (long long)blockIdx.x * 128);
}

__global__ __launch_bounds__(128, 2) void gemm_out(
    const __half* __restrict__ A, const __half* __restrict__ Bt,
    float* __restrict__ C)
{
    extern __shared__ __half sm[];
    gemm_core(A, Bt, C, 1.0f, 0, sm,
              (long long)blockIdx.y * 128, (long long)blockIdx.x * 128);
}

// ===========================================================================
// Flash attention, fp16 mma, exp2-domain softmax. R9 structure: CTA = 128
// q-rows, 4 warps, warp tile 32x64, Q fragments HOISTED (2 CTAs/SM), fp32
// bias (x log2e at prefetch, hidden under PV), 3-stage KV ring.
// ===========================================================================
#define PK 72

__global__ __launch_bounds__(128, 2) void attn_h(
    const __half* __restrict__ Q, const __half* __restrict__ K,
    const __half* __restrict__ V, const float* __restrict__ bias,
    __half* __restrict__ O)
{
    extern __shared__ __half sm[];
    __half* Qs = sm;                          // [128][72]
    __half* Ks = Qs + 128 * PK;               // [3][64][72]
    __half* Vs = Ks + 3 * 64 * PK;            // [3][64][72]

    const int tid = threadIdx.x, lane = tid & 31, wid = tid >> 5;
    const int tg = lane >> 2, tk = lane & 3;
    const int bh = blockIdx.y, b = bh >> 4, h = bh & 15;
    const int q0 = blockIdx.x * 128;
    const int wq0 = wid * 32;

    const __half* qbase = Q + ((long long)(b * LL + q0)) * DD + h * DHH;
    const __half* kbase = K + ((long long)(b * LL)) * DD + h * DHH;
    const __half* vbase = V + ((long long)(b * LL)) * DD + h * DHH;
    const float*  brow  = bias + (long long)(q0 + wq0 + tg) * LL + 2 * tk;

    const int aOffQ = (wq0 + (lane & 15)) * PK + ((lane & 16) ? 8 : 0);
    const int bOffK = ((lane & 7) + ((lane & 16) ? 8 : 0)) * PK + ((lane & 8) ? 8 : 0);
    const int bOffV = ((lane & 7) + ((lane & 8) ? 8 : 0)) * PK + ((lane & 16) ? 8 : 0);

    auto stageKV = [&](int buf, int kt) {
        __half* ks = Ks + buf * 64 * PK;
        __half* vs = Vs + buf * 64 * PK;
        const int k0 = kt * 64;
        #pragma unroll
        for (int it = 0; it < 4; it++) {
            int f = it * 128 + tid, row = f >> 3, ch = f & 7;
            cp_async16(smem_u32(ks + row * PK + ch * 8),
                       kbase + (long long)(k0 + row) * DD + ch * 8);
            cp_async16(smem_u32(vs + row * PK + ch * 8),
                       vbase + (long long)(k0 + row) * DD + ch * 8);
        }
    };

    #pragma unroll
    for (int it = 0; it < 8; it++) {
        int f = it * 128 + tid, row = f >> 3, ch = f & 7;
        cp_async16(smem_u32(Qs + row * PK + ch * 8),
                   qbase + (long long)row * DD + ch * 8);
    }
    stageKV(0, 0);
    CP_COMMIT();
    stageKV(1, 1);
    CP_COMMIT();

    float m[2][2], l[2][2];
    float o[2][8][4];
    #pragma unroll
    for (int mi = 0; mi < 2; mi++) {
        m[mi][0] = -INFINITY; m[mi][1] = -INFINITY;
        l[mi][0] = 0.f;       l[mi][1] = 0.f;
        #pragma unroll
        for (int j = 0; j < 8; j++)
            #pragma unroll
            for (int r = 0; r < 4; r++) o[mi][j][r] = 0.f;
    }

    float s[2][8][4];
    auto load_bias = [&](int kt) {   // bias * log2e (exp2-domain)
        #pragma unroll
        for (int mi = 0; mi < 2; mi++) {
            const float* bp = brow + (long long)(mi * 16) * LL + kt * 64;
            #pragma unroll
            for (int nj = 0; nj < 8; nj++) {
                float2 b0 = *reinterpret_cast<const float2*>(bp + nj * 8);
                float2 b1 = *reinterpret_cast<const float2*>(bp + 8 * (long long)LL + nj * 8);
                s[mi][nj][0] = b0.x * LOG2E; s[mi][nj][1] = b0.y * LOG2E;
                s[mi][nj][2] = b1.x * LOG2E; s[mi][nj][3] = b1.y * LOG2E;
            }
        }
    };
    load_bias(0);

    CP_WAIT1();
    __syncthreads();
    // Hoist Q fragments (loop-invariant) — R9 config
    uint32_t qf[2][4][4];
    {
        const uint32_t qBase = smem_u32(Qs + aOffQ);
        #pragma unroll
        for (int mi = 0; mi < 2; mi++)
            #pragma unroll
            for (int k16 = 0; k16 < 4; k16++)
                LDSM_X4(qf[mi][k16], qBase + (mi * 16 * PK + k16 * 16) * 2);
    }

    const int NT = LL / 64;  // 32
    for (int kt = 0; kt < NT; kt++) {
        if (kt > 0) {
            if (kt + 1 < NT) { CP_WAIT1(); } else { CP_WAIT0(); }
            __syncthreads();
        }
        if (kt + 2 < NT) { stageKV((kt + 2) % 3, kt + 2); CP_COMMIT(); }

        int buf = kt % 3;
        const uint32_t kBase = smem_u32(Ks + buf * 64 * PK + bOffK);
        const uint32_t vBase = smem_u32(Vs + buf * 64 * PK + bOffV);

        // S = bias*log2e + Q' @ K^T  (Q' pre-scaled by 0.125*log2e)
        #pragma unroll
        for (int k16 = 0; k16 < 4; k16++) {
            #pragma unroll
            for (int p = 0; p < 4; p++) {
                uint32_t bv[4];
                LDSM_X4(bv, kBase + (p * 16 * PK + k16 * 16) * 2);
                #pragma unroll
                for (int mi = 0; mi < 2; mi++) {
                    mma_f16(s[mi][2 * p],     qf[mi][k16][0], qf[mi][k16][1],
                            qf[mi][k16][2], qf[mi][k16][3], bv[0], bv[1]);
                    mma_f16(s[mi][2 * p + 1], qf[mi][k16][0], qf[mi][k16][1],
                            qf[mi][k16][2], qf[mi][k16][3], bv[2], bv[3]);
                }
            }
        }

        // Online softmax (exp2 domain) per m-fragment
        uint32_t pv[2][4][4];
        #pragma unroll
        for (int mi = 0; mi < 2; mi++) {
            float r0 = -INFINITY, r1 = -INFINITY;
            #pragma unroll
            for (int nj = 0; nj < 8; nj++) {
                r0 = fmaxf(r0, fmaxf(s[mi][nj][0], s[mi][nj][1]));
                r1 = fmaxf(r1, fmaxf(s[mi][nj][2], s[mi][nj][3]));
            }
            r0 = fmaxf(r0, __shfl_xor_sync(0xffffffffu, r0, 1));
            r0 = fmaxf(r0, __shfl_xor_sync(0xffffffffu, r0, 2));
            r1 = fmaxf(r1, __shfl_xor_sync(0xffffffffu, r1, 1));
            r1 = fmaxf(r1, __shfl_xor_sync(0xffffffffu, r1, 2));
            float m0n = fmaxf(m[mi][0], r0), m1n = fmaxf(m[mi][1], r1);
            float al0 = ex2(m[mi][0] - m0n), al1 = ex2(m[mi][1] - m1n);
            float s0 = 0.f, s1 = 0.f;
            #pragma unroll
            for (int nj = 0; nj < 8; nj++) {
                s[mi][nj][0] = ex2(s[mi][nj][0] - m0n);
                s[mi][nj][1] = ex2(s[mi][nj][1] - m0n);
                s[mi][nj][2] = ex2(s[mi][nj][2] - m1n);
                s[mi][nj][3] = ex2(s[mi][nj][3] - m1n);
                s0 += s[mi][nj][0] + s[mi][nj][1];
                s1 += s[mi][nj][2] + s[mi][nj][3];
            }
            s0 += __shfl_xor_sync(0xffffffffu, s0, 1);
            s0 += __shfl_xor_sync(0xffffffffu, s0, 2);
            s1 += __shfl_xor_sync(0xffffffffu, s1, 1);
            s1 += __shfl_xor_sync(0xffffffffu, s1, 2);
            l[mi][0] = l[mi][0] * al0 + s0;
            l[mi][1] = l[mi][1] * al1 + s1;
            m[mi][0] = m0n;  m[mi][1] = m1n;
            #pragma unroll
            for (int nj = 0; nj < 8; nj++) {
                o[mi][nj][0] *= al0; o[mi][nj][1] *= al0;
                o[mi][nj][2] *= al1; o[mi][nj][3] *= al1;
            }
            #pragma unroll
            for (int j = 0; j < 4; j++) {
                pv[mi][j][0] = pack_h2(s[mi][2 * j][0],     s[mi][2 * j][1]);
                pv[mi][j][1] = pack_h2(s[mi][2 * j][2],     s[mi][2 * j][3]);
                pv[mi][j][2] = pack_h2(s[mi][2 * j + 1][0], s[mi][2 * j + 1][1]);
                pv[mi][j][3] = pack_h2(s[mi][2 * j + 1][2], s[mi][2 * j + 1][3]);
            }
        }

        load_bias((kt + 1) & (NT - 1));

        // O += P @ V
        #pragma unroll
        for (int k16 = 0; k16 < 4; k16++) {
            #pragma unroll
            for (int p = 0; p < 4; p++) {
                uint32_t bv[4];
                LDSM_X4_T(bv, vBase + (k16 * 16 * PK + p * 16) * 2);
                #pragma unroll
                for (int mi = 0; mi < 2; mi++) {
                    mma_f16(o[mi][2 * p],     pv[mi][k16][0], pv[mi][k16][1],
                            pv[mi][k16][2], pv[mi][k16][3], bv[0], bv[1]);
                    mma_f16(o[mi][2 * p + 1], pv[mi][k16][0], pv[mi][k16][1],
                            pv[mi][k16][2], pv[mi][k16][3], bv[2], bv[3]);
                }
            }
        }
    }

    #pragma unroll
    for (int mi = 0; mi < 2; mi++) {
        float inv0 = 1.f / l[mi][0], inv1 = 1.f / l[mi][1];
        __half* ob = O + ((long long)(b * LL + q0 + wq0 + mi * 16 + tg)) * DD + h * DHH;
        #pragma unroll
        for (int nj = 0; nj < 8; nj++) {
            *reinterpret_cast<__half2*>(&ob[nj * 8 + 2 * tk]) =
                __floats2half2_rn(o[mi][nj][0] * inv0, o[mi][nj][1] * inv0);
            *reinterpret_cast<__half2*>(&ob[8 * DD + nj * 8 + 2 * tk]) =
                __floats2half2_rn(o[mi][nj][2] * inv1, o[mi][nj][3] * inv1);
        }
    }
}

// ---------------------------------------------------------------------------
extern "C" void kernel_launch(void* const* d_in, const int* in_sizes, int n_in,
                              void* d_out, int out_size)
{
    const float* xq   = (const float*)d_in[0];
    const float* xm   = (const float*)d_in[1];
    const float* bias = (const float*)d_in[2];
    const float* Wq   = (const float*)d_in[3];
    const float* Wk   = (const float*)d_in[4];
    const float* Wv   = (const float*)d_in[5];
    const float* Wo   = (const float*)d_in[6];
    float* out = (float*)d_out;

    __half *q, *k, *v, *attn, *hxq, *hxm, *twq, *twk, *twv, *two;
    cudaGetSymbolAddress((void**)&q,    g_q);
    cudaGetSymbolAddress((void**)&k,    g_k);
    cudaGetSymbolAddress((void**)&v,    g_v);
    cudaGetSymbolAddress((void**)&attn, g_attn);
    cudaGetSymbolAddress((void**)&hxq,  g_xq);
    cudaGetSymbolAddress((void**)&hxm,  g_xm);
    cudaGetSymbolAddress((void**)&twq,  g_wq);
    cudaGetSymbolAddress((void**)&twk,  g_wk);
    cudaGetSymbolAddress((void**)&twv,  g_wv);
    cudaGetSymbolAddress((void**)&two,  g_wo);

    // 1) Prep (2 launches)
    const int N4 = ROWS * DD / 4;
    dim3 cg((N4 + 255) / 256, 1, 2);
    convert_h2<<<cg, 256>>>(xq, hxq, xm, hxm, N4);
    dim3 tb(32, 8), tg(DD / 32, DD / 32, 4);
    transpose_h4<<<tg, tb>>>(Wq, twq, Wk, twk, Wv, twv, Wo, two);

    // 2) Fused Q/K/V projections
    const int GEMM_SMEM = 3 * 2 * TILEH * 2;  // 61440
    cudaFuncSetAttribute(gemm_qkv, cudaFuncAttributeMaxDynamicSharedMemorySize, GEMM_SMEM);
    cudaFuncSetAttribute(gemm_out, cudaFuncAttributeMaxDynamicSharedMemorySize, GEMM_SMEM);
    dim3 gq(DD / 128, ROWS / 128, 3);
    gemm_qkv<<<gq, 128, GEMM_SMEM>>>(hxq, hxm, twq, twk, twv, q, k, v);

    // 3) Attention (fp32 bias, exp2 domain, Q hoisted, 2 CTAs/SM)
    const int ATTN_SMEM = (128 * PK + 3 * 64 * PK + 3 * 64 * PK) * 2;  // 73728
    cudaFuncSetAttribute(attn_h, cudaFuncAttributeMaxDynamicSharedMemorySize, ATTN_SMEM);
    dim3 ga(LL / 128, BB * HH);
    attn_h<<<ga, 128, ATTN_SMEM>>>(q, k, v, bias, attn);

    // 4) Output projection (fp32 out — final answer)
    dim3 gg(DD / 128, ROWS / 128);
    gemm_out<<<gg, 128, GEMM_SMEM>>>(attn, two, out);
}